// round 1
// baseline (speedup 1.0000x reference)
#include <cuda_runtime.h>
#include <cuda_bf16.h>
#include <stdint.h>

// Problem shape (fixed by the dataset): N=262144, C=128, D=256
#define NMAX 262144
#define C_CLS 128
#define D_FEAT 256
#define SLICE 16384   // rows per segment-sum slice

// ---------------- scratch (no allocations allowed) ----------------
__device__ unsigned char g_labels[NMAX];
__device__ float g_sums[C_CLS * D_FEAT];
__device__ float g_counts[C_CLS];
__device__ float g_nmeans[C_CLS * D_FEAT];

// ---------------- K0: zero scratch + output ----------------
__global__ void k_zero(float* out) {
    int i = blockIdx.x * blockDim.x + threadIdx.x;
    if (i < C_CLS * D_FEAT) g_sums[i] = 0.0f;
    if (i < C_CLS) g_counts[i] = 0.0f;
    if (i == 0) out[0] = 0.0f;
}

// ---------------- K1: per-row argmax over C=128 -> uint8 label ----------------
// one warp per row; lane reads float4 => 512B coalesced per warp
__global__ void k_argmax(const float* __restrict__ logits, int N) {
    int warp = (blockIdx.x * blockDim.x + threadIdx.x) >> 5;
    int lane = threadIdx.x & 31;
    if (warp >= N) return;
    const float4* row = (const float4*)(logits + (size_t)warp * C_CLS);
    float4 v = row[lane];
    float m = v.x; int mi = lane * 4;
    if (v.y > m) { m = v.y; mi = lane * 4 + 1; }
    if (v.z > m) { m = v.z; mi = lane * 4 + 2; }
    if (v.w > m) { m = v.w; mi = lane * 4 + 3; }
    #pragma unroll
    for (int off = 16; off > 0; off >>= 1) {
        float om = __shfl_down_sync(0xffffffffu, m, off);
        int   oi = __shfl_down_sync(0xffffffffu, mi, off);
        if (om > m || (om == m && oi < mi)) { m = om; mi = oi; }  // first-index tiebreak
    }
    if (lane == 0) g_labels[warp] = (unsigned char)mi;
}

// ---------------- K2: segment sum via gather ----------------
// grid = (S slices, C classes). Each CTA: scan SLICE labels (uchar4, L2-hot),
// compact matching local row ids to smem list, then coalesced float4 gather of
// exactly those rows into register accumulators; one spread REDG per column.
__global__ __launch_bounds__(256, 4)
void k_segsum(const float* __restrict__ F, int N) {
    __shared__ unsigned short list[SLICE];   // 32KB, worst-case all rows match
    __shared__ int s_cnt;
    __shared__ float red[4][D_FEAT];         // 4KB cross-subgroup reduce

    const int tid = threadIdx.x;
    const int cls = blockIdx.y;
    const int slice_base = blockIdx.x * SLICE;
    const int slice_n = min(SLICE, N - slice_base);
    if (slice_n <= 0) return;

    if (tid == 0) s_cnt = 0;
    __syncthreads();

    // phase 1: scan labels (vectorized uchar4), append matches
    const uchar4* lab4 = (const uchar4*)(g_labels + slice_base);
    const int n4 = slice_n >> 2;  // SLICE divisible by 4 in the full-slice case
    for (int i = tid; i < n4; i += 256) {
        uchar4 L = lab4[i];
        if (L.x == cls) { int p = atomicAdd(&s_cnt, 1); list[p] = (unsigned short)(i * 4 + 0); }
        if (L.y == cls) { int p = atomicAdd(&s_cnt, 1); list[p] = (unsigned short)(i * 4 + 1); }
        if (L.z == cls) { int p = atomicAdd(&s_cnt, 1); list[p] = (unsigned short)(i * 4 + 2); }
        if (L.w == cls) { int p = atomicAdd(&s_cnt, 1); list[p] = (unsigned short)(i * 4 + 3); }
    }
    // tail (only for a ragged final slice)
    for (int i = n4 * 4 + tid; i < slice_n; i += 256) {
        if (g_labels[slice_base + i] == cls) {
            int p = atomicAdd(&s_cnt, 1); list[p] = (unsigned short)i;
        }
    }
    __syncthreads();

    const int nm = s_cnt;
    // phase 2: gather. 256 threads = 4 row-subgroups x 64 float4 columns.
    const int sub = tid >> 6;        // 0..3
    const int col = tid & 63;        // float4 column
    float4 acc = make_float4(0.f, 0.f, 0.f, 0.f);
    int k = sub;
    #pragma unroll 4
    for (; k + 12 < nm; k += 16) {   // 4 independent loads in flight per thread
        int r0 = slice_base + list[k];
        int r1 = slice_base + list[k + 4];
        int r2 = slice_base + list[k + 8];
        int r3 = slice_base + list[k + 12];
        float4 v0 = ((const float4*)(F + (size_t)r0 * D_FEAT))[col];
        float4 v1 = ((const float4*)(F + (size_t)r1 * D_FEAT))[col];
        float4 v2 = ((const float4*)(F + (size_t)r2 * D_FEAT))[col];
        float4 v3 = ((const float4*)(F + (size_t)r3 * D_FEAT))[col];
        acc.x += v0.x + v1.x + v2.x + v3.x;
        acc.y += v0.y + v1.y + v2.y + v3.y;
        acc.z += v0.z + v1.z + v2.z + v3.z;
        acc.w += v0.w + v1.w + v2.w + v3.w;
    }
    for (; k < nm; k += 4) {
        int r = slice_base + list[k];
        float4 v = ((const float4*)(F + (size_t)r * D_FEAT))[col];
        acc.x += v.x; acc.y += v.y; acc.z += v.z; acc.w += v.w;
    }

    // cross-subgroup reduce then spread global atomics
    red[sub][col * 4 + 0] = acc.x;
    red[sub][col * 4 + 1] = acc.y;
    red[sub][col * 4 + 2] = acc.z;
    red[sub][col * 4 + 3] = acc.w;
    __syncthreads();
    float v = red[0][tid] + red[1][tid] + red[2][tid] + red[3][tid];
    atomicAdd(&g_sums[cls * D_FEAT + tid], v);
    if (tid == 0 && nm > 0) atomicAdd(&g_counts[cls], (float)nm);
}

// ---------------- K3: means + L2 normalize ----------------
__global__ void k_norm() {
    __shared__ float s[256];
    const int c = blockIdx.x, t = threadIdx.x;
    float cnt = g_counts[c];
    float m = g_sums[c * D_FEAT + t] * (1.0f / fmaxf(cnt, 1.0f));
    s[t] = m * m;
    __syncthreads();
    for (int off = 128; off > 0; off >>= 1) {
        if (t < off) s[t] += s[t + off];
        __syncthreads();
    }
    float norm = sqrtf(s[0]);
    float inv = (norm > 0.0f) ? (1.0f / norm) : 1.0f;
    g_nmeans[c * D_FEAT + t] = m * inv;
}

// ---------------- K4: similarity + masked loss sum ----------------
__global__ void k_loss(float* out) {
    __shared__ float rowi[D_FEAT];
    __shared__ float s[128];
    const int i = blockIdx.x, j = threadIdx.x;  // 128 threads
    rowi[j] = g_nmeans[i * D_FEAT + j];
    rowi[j + 128] = g_nmeans[i * D_FEAT + j + 128];
    __syncthreads();

    const bool pi = g_counts[i] > 0.0f;
    const bool pj = g_counts[j] > 0.0f;
    float dot = 0.0f;
    const float4* rj = (const float4*)(g_nmeans + (size_t)j * D_FEAT);
    const float4* ri = (const float4*)rowi;
    #pragma unroll 8
    for (int k = 0; k < D_FEAT / 4; k++) {
        float4 a = ri[k];
        float4 b = rj[k];
        dot += a.x * b.x + a.y * b.y + a.z * b.z + a.w * b.w;
    }
    float contrib = (pi && pj && (i != j)) ? (1.0f - dot) : 0.0f;
    s[j] = contrib;
    __syncthreads();
    for (int off = 64; off > 0; off >>= 1) {
        if (j < off) s[j] += s[j + off];
        __syncthreads();
    }
    if (j == 0) atomicAdd(out, s[0]);
}

// ---------------- launch ----------------
extern "C" void kernel_launch(void* const* d_in, const int* in_sizes, int n_in,
                              void* d_out, int out_size) {
    const float* logits = (const float*)d_in[0];
    const float* feats  = (const float*)d_in[1];
    float* out = (float*)d_out;
    const int N = in_sizes[0] / C_CLS;

    k_zero<<<(C_CLS * D_FEAT + 255) / 256, 256>>>(out);

    // one warp per row, 8 rows per 256-thread block
    k_argmax<<<(N + 7) / 8, 256>>>(logits, N);

    const int S = (N + SLICE - 1) / SLICE;
    dim3 grid2(S, C_CLS);
    k_segsum<<<grid2, 256>>>(feats, N);

    k_norm<<<C_CLS, 256>>>();
    k_loss<<<C_CLS, 128>>>(out);
}